// round 17
// baseline (speedup 1.0000x reference)
#include <cuda_runtime.h>
#include <cuda_bf16.h>
#include <cstdint>

#define BB 512
#define LL 512
#define NN 128
#define EP 132      // est pitch (floats)

__device__ float g_norm[BB];
__device__ float g_path[BB];

__device__ __forceinline__ uint32_t bfpack(float lo, float hi) {
    uint32_t d;
    asm("cvt.rn.bf16x2.f32 %0, %1, %2;" : "=r"(d) : "f"(hi), "f"(lo));
    return d;
}
__device__ __forceinline__ float frcp(float x) {
    float r;
    asm("rcp.approx.f32 %0, %1;" : "=f"(r) : "f"(x));
    return r;
}
__device__ __forceinline__ uint32_t movm(uint32_t x) {
    uint32_t d;
    asm("movmatrix.sync.aligned.m8n8.trans.b16 %0, %1;" : "=r"(d) : "r"(x));
    return d;
}
__device__ __forceinline__ void mma16816(float* d,
                                         uint32_t a0, uint32_t a1, uint32_t a2, uint32_t a3,
                                         uint32_t b0, uint32_t b1) {
    asm volatile("mma.sync.aligned.m16n8k16.row.col.f32.bf16.bf16.f32 "
                 "{%0,%1,%2,%3},{%4,%5,%6,%7},{%8,%9},{%0,%1,%2,%3};"
                 : "+f"(d[0]), "+f"(d[1]), "+f"(d[2]), "+f"(d[3])
                 : "r"(a0), "r"(a1), "r"(a2), "r"(a3), "r"(b0), "r"(b1));
}

// ---------------------------------------------------------------------------
// Forward: 64 blocks x 32 threads — ONE WARP per group of 8 batches.
// C[128 x 8] = E^T @ q fully inside the warp: all 8 B k-tile frags recycled
// in registers (movmatrix of C); A = E^T, 16 tiles resident + 48 tiles read
// from smem in fragment layout (constant addresses). Emission: coalesced LDG
// 1 step ahead -> smem bounce -> scalar LDS + MUFU exp. inv via 2 shfls.
// NO BARRIERS in the 511-step loop; one __syncwarp per step.
// ---------------------------------------------------------------------------
__global__ __launch_bounds__(32, 1)
void crf_forward(const float* __restrict__ em,
                 const float* __restrict__ mask,
                 const float* __restrict__ start,
                 const float* __restrict__ trans) {
    __shared__ uint4 Afr[48][32];      // A-tile fragments, k-tiles 2..7
    __shared__ float est[2][8][EP];    // staged emission [parity][batch][state]

    const int lane = threadIdx.x;
    const int r = lane >> 2, c = lane & 3;
    const int bA = 2 * c, bB = bA + 1;
    const int b0g = blockIdx.x * 8;

    int S[8][2];
#pragma unroll
    for (int mi = 0; mi < 8; mi++) { S[mi][0] = 16 * mi + r; S[mi][1] = S[mi][0] + 8; }

    // ---- A fragments: A[j][i] = exp(trans[i*NN+j]). kt 0,1 resident ----
    uint32_t Af[8][2][4];
#pragma unroll
    for (int mi = 0; mi < 8; mi++) {
        const int j0 = S[mi][0], j1 = S[mi][1];
#pragma unroll
        for (int kt = 0; kt < 2; kt++) {
            const int i0 = 16 * kt + 2 * c;
            Af[mi][kt][0] = bfpack(__expf(trans[(i0)     * NN + j0]),
                                   __expf(trans[(i0 + 1) * NN + j0]));
            Af[mi][kt][1] = bfpack(__expf(trans[(i0)     * NN + j1]),
                                   __expf(trans[(i0 + 1) * NN + j1]));
            Af[mi][kt][2] = bfpack(__expf(trans[(i0 + 8) * NN + j0]),
                                   __expf(trans[(i0 + 9) * NN + j0]));
            Af[mi][kt][3] = bfpack(__expf(trans[(i0 + 8) * NN + j1]),
                                   __expf(trans[(i0 + 9) * NN + j1]));
        }
    }
    // kt 2..7 -> smem in fragment layout
    for (int kt = 2; kt < 8; kt++) {
#pragma unroll
        for (int mi = 0; mi < 8; mi++) {
            const int j0 = S[mi][0], j1 = S[mi][1];
            const int i0 = 16 * kt + 2 * c;
            uint4 v;
            v.x = bfpack(__expf(trans[(i0)     * NN + j0]),
                         __expf(trans[(i0 + 1) * NN + j0]));
            v.y = bfpack(__expf(trans[(i0)     * NN + j1]),
                         __expf(trans[(i0 + 1) * NN + j1]));
            v.z = bfpack(__expf(trans[(i0 + 8) * NN + j0]),
                         __expf(trans[(i0 + 9) * NN + j0]));
            v.w = bfpack(__expf(trans[(i0 + 8) * NN + j1]),
                         __expf(trans[(i0 + 9) * NN + j1]));
            Afr[(kt - 2) * 8 + mi][lane] = v;
        }
    }

    const size_t ebA = (size_t)(b0g + bA) * (LL * NN);
    const size_t ebB = (size_t)(b0g + bB) * (LL * NN);

    float qprev[8][2][2];
    uint2  bq[8];
    float Lr_A, Lr_B, invA, invB, mkA, mkB;

    // ================= init t=0 =================
    {
        float s000A = 0.f, s000B = 0.f;   // s0 at (mi=0,h=0) for shfl
        float s0[8][2][2];
#pragma unroll
        for (int mi = 0; mi < 8; mi++)
#pragma unroll
            for (int h = 0; h < 2; h++) {
                const int s = S[mi][h];
                const float st = start[s];
                s0[mi][h][0] = st + em[ebA + s];
                s0[mi][h][1] = st + em[ebB + s];
            }
        s000A = s0[0][0][0]; s000B = s0[0][0][1];
        const float cA = __shfl_sync(0xffffffffu, s000A, c);
        const float cB = __shfl_sync(0xffffffffu, s000B, c);
        Lr_A = cA; Lr_B = cB;
#pragma unroll
        for (int mi = 0; mi < 8; mi++)
#pragma unroll
            for (int h = 0; h < 2; h++) {
                qprev[mi][h][0] = __expf(s0[mi][h][0] - cA);
                qprev[mi][h][1] = __expf(s0[mi][h][1] - cB);
            }
        invA = frcp(__shfl_sync(0xffffffffu, qprev[0][0][0], c));
        invB = frcp(__shfl_sync(0xffffffffu, qprev[0][0][1], c));
#pragma unroll
        for (int mi = 0; mi < 8; mi++) {
            uint32_t u0 = bfpack(qprev[mi][0][0], qprev[mi][0][1]);
            uint32_t u1 = bfpack(qprev[mi][1][0], qprev[mi][1][1]);
            bq[mi] = make_uint2(movm(u0), movm(u1));
        }
        // stage em[1]
#pragma unroll
        for (int bb = 0; bb < 8; bb++) {
            float4 v = *(const float4*)&em[((size_t)(b0g + bb) * LL + 1) * NN + lane * 4];
            *(float4*)&est[1][bb][lane * 4] = v;
        }
        mkA = mask[(size_t)(b0g + bA) * LL + 1];
        mkB = mask[(size_t)(b0g + bB) * LL + 1];
        __syncwarp();
    }

    // ================= recurrence (NO barriers) =================
    for (int t = 1; t < LL; t++) {
        const int pr = t & 1, pw = pr ^ 1;

        // ---- LDG em[t+1] + mask[t+1] (consumed next step) ----
        const int tn = (t + 1 < LL) ? (t + 1) : (LL - 1);
        float4 ve[8];
#pragma unroll
        for (int bb = 0; bb < 8; bb++)
            ve[bb] = *(const float4*)&em[((size_t)(b0g + bb) * LL + tn) * NN + lane * 4];
        const float mkAn = mask[(size_t)(b0g + bA) * LL + tn];
        const float mkBn = mask[(size_t)(b0g + bB) * LL + tn];

        // ---- sc = exp(em[t]) * inv   (LDS + MUFU, pre-MMA) ----
        float sc[8][2][2];
#pragma unroll
        for (int mi = 0; mi < 8; mi++)
#pragma unroll
            for (int h = 0; h < 2; h++) {
                sc[mi][h][0] = __expf(est[pr][bA][S[mi][h]]) * invA;
                sc[mi][h][1] = __expf(est[pr][bB][S[mi][h]]) * invB;
            }

        // ---- MMA: 8 chains (one per m-tile), depth 8 ----
        float acc[8][4];
#pragma unroll
        for (int mi = 0; mi < 8; mi++)
#pragma unroll
            for (int i = 0; i < 4; i++) acc[mi][i] = 0.f;
#pragma unroll
        for (int kt = 0; kt < 2; kt++)
#pragma unroll
            for (int mi = 0; mi < 8; mi++)
                mma16816(acc[mi], Af[mi][kt][0], Af[mi][kt][1], Af[mi][kt][2], Af[mi][kt][3],
                         bq[kt].x, bq[kt].y);
#pragma unroll
        for (int kt = 2; kt < 8; kt++)
#pragma unroll
            for (int mi = 0; mi < 8; mi++) {
                uint4 a = Afr[(kt - 2) * 8 + mi][lane];
                mma16816(acc[mi], a.x, a.y, a.z, a.w, bq[kt].x, bq[kt].y);
            }

        // ---- epilogue (branch-free; rare fractional-mask fallback) ----
        const bool fr = ((mkA != 0.0f) && (mkA != 1.0f)) ||
                        ((mkB != 0.0f) && (mkB != 1.0f));
        if (!__any_sync(0xffffffffu, fr)) {
#pragma unroll
            for (int mi = 0; mi < 8; mi++) {
                float q0 = (mkA != 0.0f) ? acc[mi][0] * sc[mi][0][0] : qprev[mi][0][0] * invA;
                float q1 = (mkB != 0.0f) ? acc[mi][1] * sc[mi][0][1] : qprev[mi][0][1] * invB;
                float q2 = (mkA != 0.0f) ? acc[mi][2] * sc[mi][1][0] : qprev[mi][1][0] * invA;
                float q3 = (mkB != 0.0f) ? acc[mi][3] * sc[mi][1][1] : qprev[mi][1][1] * invB;
                qprev[mi][0][0] = q0; qprev[mi][0][1] = q1;
                qprev[mi][1][0] = q2; qprev[mi][1][1] = q3;
                bq[mi] = make_uint2(movm(bfpack(q0, q1)), movm(bfpack(q2, q3)));
            }
        } else {
#pragma unroll
            for (int mi = 0; mi < 8; mi++) {
                float q0 = __expf(mkA * __logf(acc[mi][0] * sc[mi][0][0]) +
                                  (1.f - mkA) * __logf(qprev[mi][0][0] * invA));
                float q1 = __expf(mkB * __logf(acc[mi][1] * sc[mi][0][1]) +
                                  (1.f - mkB) * __logf(qprev[mi][0][1] * invB));
                float q2 = __expf(mkA * __logf(acc[mi][2] * sc[mi][1][0]) +
                                  (1.f - mkA) * __logf(qprev[mi][1][0] * invA));
                float q3 = __expf(mkB * __logf(acc[mi][3] * sc[mi][1][1]) +
                                  (1.f - mkB) * __logf(qprev[mi][1][1] * invB));
                qprev[mi][0][0] = q0; qprev[mi][0][1] = q1;
                qprev[mi][1][0] = q2; qprev[mi][1][1] = q3;
                bq[mi] = make_uint2(movm(bfpack(q0, q1)), movm(bfpack(q2, q3)));
            }
        }

        // ---- log-offset (uses this step's inv), then next inv via shfl ----
        Lr_A -= __logf(invA);
        Lr_B -= __logf(invB);
        invA = frcp(__shfl_sync(0xffffffffu, qprev[0][0][0], c));
        invB = frcp(__shfl_sync(0xffffffffu, qprev[0][0][1], c));

        // ---- stage em[t+1] ----
#pragma unroll
        for (int bb = 0; bb < 8; bb++)
            *(float4*)&est[pw][bb][lane * 4] = ve[bb];
        mkA = mkAn; mkB = mkBn;
        __syncwarp();
    }

    // ================= final: normalizer = L + log(sum q) =================
    float sA = 0.f, sB = 0.f;
#pragma unroll
    for (int mi = 0; mi < 8; mi++)
#pragma unroll
        for (int h = 0; h < 2; h++) { sA += qprev[mi][h][0]; sB += qprev[mi][h][1]; }
#pragma unroll
    for (int o = 4; o <= 16; o <<= 1) {
        sA += __shfl_xor_sync(0xffffffffu, sA, o);
        sB += __shfl_xor_sync(0xffffffffu, sB, o);
    }
    if (r == 0) {
        g_norm[b0g + bA] = Lr_A + __logf(sA);
        g_norm[b0g + bB] = Lr_B + __logf(sB);
    }
}

// ---------------------------------------------------------------------------
// Path score. One block (128 threads) per batch.
// ---------------------------------------------------------------------------
__global__ __launch_bounds__(128)
void crf_path(const float* __restrict__ em,
              const int*   __restrict__ tgt,
              const float* __restrict__ mask,
              const float* __restrict__ start,
              const float* __restrict__ trans) {
    const int bb = blockIdx.x;
    const int tid = threadIdx.x;
    __shared__ float red[128];

    const size_t embase = (size_t)bb * LL * NN;
    float s = 0.0f;
    for (int t = tid; t < LL; t += 128) {
        if (t == 0) {
            int t0 = tgt[bb * LL];
            s += start[t0] + em[embase + t0];
        } else {
            int prev = tgt[bb * LL + t - 1];
            int cur  = tgt[bb * LL + t];
            s += mask[bb * LL + t] *
                 (trans[prev * NN + cur] + em[embase + (size_t)t * NN + cur]);
        }
    }
    red[tid] = s;
    __syncthreads();
#pragma unroll
    for (int o = 64; o; o >>= 1) {
        if (tid < o) red[tid] += red[tid + o];
        __syncthreads();
    }
    if (tid == 0) g_path[bb] = red[0];
}

// ---------------------------------------------------------------------------
// mean(normalizer - path)
// ---------------------------------------------------------------------------
__global__ __launch_bounds__(512)
void crf_final(float* __restrict__ out) {
    const int tid = threadIdx.x;
    __shared__ float wsum[16];
    float v = g_norm[tid] - g_path[tid];
#pragma unroll
    for (int o = 16; o; o >>= 1) v += __shfl_xor_sync(0xffffffffu, v, o);
    if ((tid & 31) == 0) wsum[tid >> 5] = v;
    __syncthreads();
    if (tid < 32) {
        float x = (tid < 16) ? wsum[tid] : 0.0f;
#pragma unroll
        for (int o = 8; o; o >>= 1) x += __shfl_xor_sync(0xffffffffu, x, o);
        if (tid == 0) out[0] = x * (1.0f / (float)BB);
    }
}

// ---------------------------------------------------------------------------
// Launch
// ---------------------------------------------------------------------------
extern "C" void kernel_launch(void* const* d_in, const int* in_sizes, int n_in,
                              void* d_out, int out_size) {
    const float* emission    = (const float*)d_in[0];
    const int*   target      = (const int*)  d_in[1];
    const float* mask        = (const float*)d_in[2];
    const float* start_trans = (const float*)d_in[3];
    const float* trans       = (const float*)d_in[4];
    float* out = (float*)d_out;

    crf_forward<<<64, 32>>>(emission, mask, start_trans, trans);
    crf_path<<<BB, 128>>>(emission, target, mask, start_trans, trans);
    crf_final<<<1, 512>>>(out);
}